// round 9
// baseline (speedup 1.0000x reference)
#include <cuda_runtime.h>

// Problem constants
#define BB 256
#define TT 4096
#define HH 64
#define TPB 256
#define CHUNKS (TT / TPB)           // 16
#define NBLOCKS (BB * CHUNKS)       // 4096
#define NC 16                       // Chebyshev nodes / coeffs (degree 15)
#define NPOLY 32                    // 16 latent + 16 dlatent
#define DPI 3.14159265358979323846

typedef unsigned long long ull;

// Deterministic scratch (no atomics, no allocation)
__device__ float g_partial[NBLOCKS];
__device__ ull   g_C[NC * 16];      // [m][e] : packed (poly 2e, poly 2e+1) monomial coeff m

__device__ __forceinline__ ull pack2(float lo, float hi) {
    ull r; asm("mov.b64 %0, {%1, %2};" : "=l"(r) : "f"(lo), "f"(hi)); return r;
}
__device__ __forceinline__ void unpack2(ull v, float& lo, float& hi) {
    asm("mov.b64 {%0, %1}, %2;" : "=f"(lo), "=f"(hi) : "l"(v));
}
__device__ __forceinline__ ull fma2(ull a, ull b, ull c) {
    ull d; asm("fma.rn.f32x2 %0, %1, %2, %3;" : "=l"(d) : "l"(a), "l"(b), "l"(c)); return d;
}
__device__ __forceinline__ ull add2(ull a, ull b) {
    ull d; asm("add.rn.f32x2 %0, %1, %2;" : "=l"(d) : "l"(a), "l"(b)); return d;
}
__device__ __forceinline__ ull mul2(ull a, ull b) {
    ull d; asm("mul.rn.f32x2 %0, %1, %2;" : "=l"(d) : "l"(a), "l"(b)); return d;
}
__device__ __forceinline__ ull sub2(ull a, ull b) {
    return add2(a, b ^ 0x8000000080000000ULL);
}

// ───────────────────────────── prep: fit degree-15 polynomials ─────────────
// poly j (0..15)  = latent_j(t)  (includes b2)
// poly j (16..31) = d latent_{j-16} / dt
__global__ __launch_bounds__(512) void pinn_prep(
    const float* __restrict__ W1, const float* __restrict__ b1,
    const float* __restrict__ W2, const float* __restrict__ b2)
{
    __shared__ double sF[NPOLY][NC];   // node values
    __shared__ double sC[NPOLY][NC];   // Chebyshev coeffs
    __shared__ double sT[NC][NC];      // T_m monomial coeffs
    __shared__ float  sA[NPOLY][NC];   // monomial coeffs

    const int tid = threadIdx.x;       // 512 = 32 polys x 16 nodes
    const int j = tid >> 4;            // poly
    const int i = tid & 15;            // node / coeff index

    // Phase 1: exact values at Chebyshev nodes  t = 0.5 + 0.5*cos(theta)
    {
        const double u  = cos(DPI * (2 * i + 1) / (2.0 * NC));
        const float  tv = (float)(0.5 + 0.5 * u);
        const int jj = j & 15;
        const bool isD = (j >= 16);
        double acc = isD ? 0.0 : (double)b2[jj];
        for (int k = 0; k < HH; ++k) {
            const float w1k = W1[k];
            const float h = tanhf(fmaf(tv, w1k, b1[k]));
            const float wkj = W2[k * 16 + jj];
            const float v = isD ? ((1.0f - h * h) * w1k * wkj) : (h * wkj);
            acc += (double)v;
        }
        sF[j][i] = acc;
    }
    __syncthreads();

    // Phase 2: DCT -> Chebyshev coefficients (m = i)
    {
        const int m = i;
        double s = 0.0;
        for (int q = 0; q < NC; ++q)
            s += sF[j][q] * cos(DPI * m * (2 * q + 1) / (2.0 * NC));
        sC[j][m] = s * ((m == 0) ? (1.0 / NC) : (2.0 / NC));
    }
    __syncthreads();

    // Phase 3: T_m monomial-coefficient table (fp64, one thread)
    if (tid == 0) {
        for (int m = 0; m < NC; ++m)
            for (int p = 0; p < NC; ++p) sT[m][p] = 0.0;
        sT[0][0] = 1.0;
        sT[1][1] = 1.0;
        for (int m = 2; m < NC; ++m)
            for (int p = 0; p < NC; ++p) {
                double v = -sT[m - 2][p];
                if (p > 0) v += 2.0 * sT[m - 1][p - 1];
                sT[m][p] = v;
            }
    }
    __syncthreads();

    // Phase 4: Chebyshev -> monomial in u (p = i), fp64 then narrow
    {
        const int p = i;
        double a = 0.0;
        for (int m = p; m < NC; ++m) a += sC[j][m] * sT[m][p];
        sA[j][p] = (float)a;
    }
    __syncthreads();

    // Phase 5: pack j-pairs: g_C[m*16 + e] = (poly 2e, poly 2e+1) coeff m
    if (tid < NC * 16) {
        const int m = tid >> 4, e = tid & 15;
        g_C[m * 16 + e] = pack2(sA[2 * e][m], sA[2 * e + 1][m]);
    }
}

// ───────────────────────────── point kernel ────────────────────────────────
__global__ __launch_bounds__(TPB) void pinn_point_kernel(
    const float* __restrict__ t,
    const float* __restrict__ x_target,
    const float* __restrict__ params_pred,
    const float* __restrict__ params_target,
    const float* __restrict__ ic_pred,
    const float* __restrict__ ic_target)
{
    __shared__ ull  sCm[NC * 16];   // [m][e], 2KB
    __shared__ ull  sPi2[8 * 4];    // [j][e] = (Pi[2e][j], Pi[2e+1][j])
    __shared__ ull  sGa2[8 * 4];    // [j][e] = (Ga[2e][j], Ga[2e+1][j])
    __shared__ ull  sG2[4];         // g pairs
    __shared__ ull  sMu2[4];        // mu pairs
    __shared__ float sMu[8];

    const int b     = blockIdx.x >> 4;
    const int chunk = blockIdx.x & (CHUNKS - 1);
    const int tid   = threadIdx.x;
    const float* pp = params_pred + b * 144;

    // Stage coefficients + packed per-batch params
    sCm[tid] = g_C[tid];                          // 256 == TPB
    if (tid < 32) {                               // Pi packed by row-pairs
        const int jj = tid >> 2, e = tid & 3;
        sPi2[jj * 4 + e] = pack2(pp[16 + (2 * e) * 8 + jj], pp[16 + (2 * e + 1) * 8 + jj]);
    } else if (tid < 64) {                        // Gamma packed by row-pairs
        const int q = tid - 32, jj = q >> 2, e = q & 3;
        sGa2[jj * 4 + e] = pack2(pp[80 + (2 * e) * 8 + jj], pp[80 + (2 * e + 1) * 8 + jj]);
    } else if (tid < 68) {
        const int e = tid - 64; sG2[e] = pack2(pp[2 * e], pp[2 * e + 1]);
    } else if (tid < 72) {
        const int e = tid - 68; sMu2[e] = pack2(pp[8 + 2 * e], pp[8 + 2 * e + 1]);
    } else if (tid < 80) {
        sMu[tid - 72] = pp[8 + (tid - 72)];
    }
    __syncthreads();

    const int   ti = chunk * TPB + tid;
    const float tv = t[b * TT + ti];
    const float u  = fmaf(2.0f, tv, -1.0f);
    const ull   uu = pack2(u, u);

    // 16 packed Horner evaluations (lat pairs e=0..7, dlat pairs e=8..15)
    const ulonglong2* C2 = (const ulonglong2*)sCm;
    ull acc[16];
    #pragma unroll
    for (int f = 0; f < 8; ++f) {
        const ulonglong2 c = C2[15 * 8 + f];
        acc[2 * f] = c.x; acc[2 * f + 1] = c.y;
    }
    #pragma unroll
    for (int m = 14; m >= 0; --m) {
        #pragma unroll
        for (int f = 0; f < 8; ++f) {
            const ulonglong2 c = C2[m * 8 + f];
            acc[2 * f]     = fma2(uu, acc[2 * f],     c.x);
            acc[2 * f + 1] = fma2(uu, acc[2 * f + 1], c.y);
        }
    }
    // acc[0..3]: a-part st pairs | acc[4..7]: q pairs | acc[8..11]: ds a-part | acc[12..15]: ds x raw

    // Relu gate (scalar), rebuild packed x-part
    float q[8], dq[8], xv[8], dsx[8];
    #pragma unroll
    for (int f = 0; f < 4; ++f) {
        unpack2(acc[4 + f],  q[2 * f],  q[2 * f + 1]);
        unpack2(acc[12 + f], dq[2 * f], dq[2 * f + 1]);
    }
    #pragma unroll
    for (int jj = 0; jj < 8; ++jj) {
        const float r = q[jj] - sMu[jj];
        const bool pos = (r > 0.0f);            // JAX relu jvp convention
        xv[jj]  = pos ? r : 0.0f;
        dsx[jj] = pos ? dq[jj] : 0.0f;
    }
    ull stX2[4], dsX2[4], xx[8], aa[8];
    #pragma unroll
    for (int f = 0; f < 4; ++f) {
        stX2[f] = pack2(xv[2 * f],  xv[2 * f + 1]);
        dsX2[f] = pack2(dsx[2 * f], dsx[2 * f + 1]);
    }
    #pragma unroll
    for (int jj = 0; jj < 8; ++jj) xx[jj] = pack2(xv[jj], xv[jj]);
    {
        float a_[8];
        #pragma unroll
        for (int f = 0; f < 4; ++f) unpack2(acc[f], a_[2 * f], a_[2 * f + 1]);
        #pragma unroll
        for (int jj = 0; jj < 8; ++jj) aa[jj] = pack2(a_[jj], a_[jj]);
    }

    // Data loss (packed pairs)
    ull err2 = 0ull;
    const float* xt = x_target + (size_t)b * 16 * TT + ti;
    #pragma unroll
    for (int f = 0; f < 4; ++f) {
        const ull d = sub2(acc[f], pack2(xt[(2 * f) * TT], xt[(2 * f + 1) * TT]));
        err2 = fma2(d, d, err2);
    }
    #pragma unroll
    for (int f = 0; f < 4; ++f) {
        const ull d = sub2(stX2[f], pack2(xt[(8 + 2 * f) * TT], xt[(8 + 2 * f + 1) * TT]));
        err2 = fma2(d, d, err2);
    }

    // Physics (packed row-pairs): da = g + Pi@x - a ; dx = (Gamma@a)*(mu - x)
    #pragma unroll
    for (int e = 0; e < 4; ++e) {
        ull pacc = sG2[e];
        #pragma unroll
        for (int jj = 0; jj < 8; ++jj)
            pacc = fma2(sPi2[jj * 4 + e], xx[jj], pacc);
        const ull da2 = sub2(pacc, acc[e]);
        const ull d1  = sub2(acc[8 + e], da2);
        err2 = fma2(d1, d1, err2);

        ull gacc = 0ull;
        #pragma unroll
        for (int jj = 0; jj < 8; ++jj)
            gacc = fma2(sGa2[jj * 4 + e], aa[jj], gacc);
        const ull mux = sub2(sMu2[e], stX2[e]);
        const ull dx2 = mul2(gacc, mux);
        const ull d2v = sub2(dsX2[e], dx2);
        err2 = fma2(d2v, d2v, err2);
    }
    float elo, ehi; unpack2(err2, elo, ehi);
    float err = elo + ehi;

    // Supervised slice: 9 params elems + 1 ic elem per block
    float sup = 0.0f;
    if (tid < 9) {
        const int i = blockIdx.x * 9 + tid;
        const float d = params_pred[i] - params_target[i];
        sup = d * d;
    } else if (tid == 9) {
        const float d = ic_pred[blockIdx.x] - ic_target[blockIdx.x];
        sup = d * d;
    }

    // Deterministic block reduction
    #pragma unroll
    for (int off = 16; off; off >>= 1) {
        err += __shfl_xor_sync(0xffffffffu, err, off);
        sup += __shfl_xor_sync(0xffffffffu, sup, off);
    }
    __shared__ float sr1[TPB / 32], sr2[TPB / 32];
    if ((tid & 31) == 0) { sr1[tid >> 5] = err; sr2[tid >> 5] = sup; }
    __syncthreads();
    if (tid == 0) {
        float s = 0.0f, ss = 0.0f;
        #pragma unroll
        for (int w = 0; w < TPB / 32; ++w) { s += sr1[w]; ss += sr2[w]; }
        g_partial[blockIdx.x] = s * (1.0f / 16777216.0f) + ss * (1.0f / 40960.0f);
    }
}

__global__ __launch_bounds__(256) void pinn_finalize(float* __restrict__ out)
{
    const int tid = threadIdx.x;
    const float4* p = (const float4*)g_partial;      // 1024 float4
    float s = 0.0f;
    #pragma unroll
    for (int i = tid; i < NBLOCKS / 4; i += 256) {
        const float4 v = p[i];
        s += (v.x + v.y) + (v.z + v.w);
    }
    #pragma unroll
    for (int off = 16; off; off >>= 1)
        s += __shfl_xor_sync(0xffffffffu, s, off);
    __shared__ float r[8];
    if ((tid & 31) == 0) r[tid >> 5] = s;
    __syncthreads();
    if (tid == 0) {
        float a = 0.0f;
        #pragma unroll
        for (int w = 0; w < 8; ++w) a += r[w];
        out[0] = a;
    }
}

extern "C" void kernel_launch(void* const* d_in, const int* in_sizes, int n_in,
                              void* d_out, int out_size) {
    const float* t             = (const float*)d_in[0];
    const float* x_target      = (const float*)d_in[1];
    const float* params_pred   = (const float*)d_in[2];
    const float* params_target = (const float*)d_in[3];
    const float* ic_pred       = (const float*)d_in[4];
    const float* ic_target     = (const float*)d_in[5];
    const float* W1            = (const float*)d_in[6];
    const float* b1            = (const float*)d_in[7];
    const float* W2            = (const float*)d_in[8];
    const float* b2            = (const float*)d_in[9];

    pinn_prep<<<1, 512>>>(W1, b1, W2, b2);
    pinn_point_kernel<<<NBLOCKS, TPB>>>(t, x_target, params_pred, params_target,
                                        ic_pred, ic_target);
    pinn_finalize<<<1, 256>>>((float*)d_out);
}

// round 11
// speedup vs baseline: 1.7628x; 1.7628x over previous
#include <cuda_runtime.h>

// Problem constants
#define BB 256
#define TT 4096
#define HH 64
#define TPB 256
#define CHUNKS (TT / TPB)           // 16
#define NBLOCKS (BB * CHUNKS)       // 4096
#define NC 16                       // Chebyshev fit nodes (degree 15 fit)
#define NCOEF 12                    // retained monomial coeffs (degree 11, economized)
#define NPOLY 32                    // 16 latent + 16 dlatent

typedef unsigned long long ull;

// Deterministic scratch (no atomics, no allocation)
__device__ float g_partial[NBLOCKS];
__device__ ull   g_C[NCOEF * 16];   // [m][e] : packed (poly 2e, poly 2e+1) monomial coeff m

__device__ __forceinline__ ull pack2(float lo, float hi) {
    ull r; asm("mov.b64 %0, {%1, %2};" : "=l"(r) : "f"(lo), "f"(hi)); return r;
}
__device__ __forceinline__ void unpack2(ull v, float& lo, float& hi) {
    asm("mov.b64 {%0, %1}, %2;" : "=f"(lo), "=f"(hi) : "l"(v));
}
__device__ __forceinline__ ull fma2(ull a, ull b, ull c) {
    ull d; asm("fma.rn.f32x2 %0, %1, %2, %3;" : "=l"(d) : "l"(a), "l"(b), "l"(c)); return d;
}
__device__ __forceinline__ ull add2(ull a, ull b) {
    ull d; asm("add.rn.f32x2 %0, %1, %2;" : "=l"(d) : "l"(a), "l"(b)); return d;
}
__device__ __forceinline__ ull mul2(ull a, ull b) {
    ull d; asm("mul.rn.f32x2 %0, %1, %2;" : "=l"(d) : "l"(a), "l"(b)); return d;
}
__device__ __forceinline__ ull sub2(ull a, ull b) {
    return add2(a, b ^ 0x8000000080000000ULL);
}

// ───────────────────────────── prep: fit polynomials ───────────────────────
// poly j (0..15)  = latent_j(t)  (includes b2) ; poly j (16..31) = d latent/dt
__global__ __launch_bounds__(512) void pinn_prep(
    const float* __restrict__ W1, const float* __restrict__ b1,
    const float* __restrict__ W2, const float* __restrict__ b2)
{
    __shared__ double sCos[64];        // cos(pi*k/32), k=0..63
    __shared__ double sF[NPOLY][NC];   // node values
    __shared__ double sC[NPOLY][NC];   // Chebyshev coeffs
    __shared__ double sT[NC][NC];      // T_m monomial coeffs (exact integers)
    __shared__ float  sA[NPOLY][NCOEF];// monomial coeffs

    const int tid = threadIdx.x;       // 512 = 32 polys x 16 nodes
    const int j = tid >> 4;            // poly
    const int i = tid & 15;            // node / coeff index

    // Phase 0: cosine table (the ONLY fp64 cos calls, all parallel)
    if (tid < 64) sCos[tid] = cospi((double)tid / 32.0);
    __syncthreads();

    // Phase 1: exact values at Chebyshev nodes  t = 0.5 + 0.5*cos(pi(2i+1)/32)
    {
        const float tv = (float)(0.5 + 0.5 * sCos[2 * i + 1]);
        const int jj = j & 15;
        const bool isD = (j >= 16);
        double acc = isD ? 0.0 : (double)b2[jj];
        for (int k = 0; k < HH; ++k) {
            const float w1k = W1[k];
            const float h = tanhf(fmaf(tv, w1k, b1[k]));
            const float wkj = W2[k * 16 + jj];
            const float v = isD ? ((1.0f - h * h) * w1k * wkj) : (h * wkj);
            acc += (double)v;
        }
        sF[j][i] = acc;
    }
    __syncthreads();

    // Phase 2: DCT -> Chebyshev coeffs via table: cos(pi*m*(2q+1)/32) = sCos[(m*(2q+1)) & 63]
    {
        const int m = i;
        double s = 0.0;
        #pragma unroll
        for (int q = 0; q < NC; ++q)
            s += sF[j][q] * sCos[(m * (2 * q + 1)) & 63];
        sC[j][m] = s * ((m == 0) ? (1.0 / NC) : (2.0 / NC));
    }

    // Phase 3: T_m monomial table, parallel recurrence (16 threads/row, 14 syncs)
    if (tid < NC * 2) {                // zero rows 0,1 then seed
        const int m = tid >> 4, p = tid & 15;
        sT[m][p] = 0.0;
    }
    __syncthreads();
    if (tid == 0) sT[0][0] = 1.0;
    if (tid == 1) sT[1][1] = 1.0;
    for (int m = 2; m < NC; ++m) {
        __syncthreads();
        if (tid < NC) {
            const int p = tid;
            double v = -sT[m - 2][p];
            if (p > 0) v += 2.0 * sT[m - 1][p - 1];
            sT[m][p] = v;
        }
    }
    __syncthreads();

    // Phase 4: economized Chebyshev -> monomial (keep m < NCOEF), fp64 then narrow
    if (i < NCOEF) {
        const int p = i;
        double a = 0.0;
        for (int m = p; m < NCOEF; ++m) a += sC[j][m] * sT[m][p];
        sA[j][p] = (float)a;
    }
    __syncthreads();

    // Phase 5: pack j-pairs: g_C[m*16 + e] = (poly 2e, poly 2e+1) coeff m
    if (tid < NCOEF * 16) {
        const int m = tid >> 4, e = tid & 15;
        g_C[m * 16 + e] = pack2(sA[2 * e][m], sA[2 * e + 1][m]);
    }
}

// ───────────────────────────── point kernel ────────────────────────────────
__global__ __launch_bounds__(TPB) void pinn_point_kernel(
    const float* __restrict__ t,
    const float* __restrict__ x_target,
    const float* __restrict__ params_pred,
    const float* __restrict__ params_target,
    const float* __restrict__ ic_pred,
    const float* __restrict__ ic_target)
{
    __shared__ ull  sCm[NCOEF * 16]; // [m][e]
    __shared__ ull  sPi2[8 * 4];     // [j][e] = (Pi[2e][j], Pi[2e+1][j])
    __shared__ ull  sGa2[8 * 4];     // [j][e] = (Ga[2e][j], Ga[2e+1][j])
    __shared__ ull  sG2[4];          // g pairs
    __shared__ ull  sMu2[4];         // mu pairs
    __shared__ float sMu[8];

    const int b     = blockIdx.x >> 4;
    const int chunk = blockIdx.x & (CHUNKS - 1);
    const int tid   = threadIdx.x;
    const float* pp = params_pred + b * 144;

    // Stage coefficients + packed per-batch params
    if (tid < NCOEF * 16) sCm[tid] = g_C[tid];
    if (tid >= 192 && tid < 224) {                // Pi packed by row-pairs
        const int q2 = tid - 192, jj = q2 >> 2, e = q2 & 3;
        sPi2[jj * 4 + e] = pack2(pp[16 + (2 * e) * 8 + jj], pp[16 + (2 * e + 1) * 8 + jj]);
    } else if (tid >= 224) {                      // Gamma packed by row-pairs
        const int q2 = tid - 224, jj = q2 >> 2, e = q2 & 3;
        sGa2[jj * 4 + e] = pack2(pp[80 + (2 * e) * 8 + jj], pp[80 + (2 * e + 1) * 8 + jj]);
    } else if (tid >= 176 && tid < 180) {
        const int e = tid - 176; sG2[e] = pack2(pp[2 * e], pp[2 * e + 1]);
    } else if (tid >= 180 && tid < 184) {
        const int e = tid - 180; sMu2[e] = pack2(pp[8 + 2 * e], pp[8 + 2 * e + 1]);
    } else if (tid >= 184 && tid < 192) {
        sMu[tid - 184] = pp[8 + (tid - 184)];
    }
    __syncthreads();

    const int   ti = chunk * TPB + tid;
    const float tv = t[b * TT + ti];
    const float u  = fmaf(2.0f, tv, -1.0f);
    const ull   uu = pack2(u, u);

    // 16 packed Horner evaluations (lat pairs e=0..7, dlat pairs e=8..15)
    const ulonglong2* C2 = (const ulonglong2*)sCm;
    ull acc[16];
    #pragma unroll
    for (int f = 0; f < 8; ++f) {
        const ulonglong2 c = C2[(NCOEF - 1) * 8 + f];
        acc[2 * f] = c.x; acc[2 * f + 1] = c.y;
    }
    #pragma unroll
    for (int m = NCOEF - 2; m >= 0; --m) {
        #pragma unroll
        for (int f = 0; f < 8; ++f) {
            const ulonglong2 c = C2[m * 8 + f];
            acc[2 * f]     = fma2(uu, acc[2 * f],     c.x);
            acc[2 * f + 1] = fma2(uu, acc[2 * f + 1], c.y);
        }
    }
    // acc[0..3]: a-part st pairs | acc[4..7]: q pairs | acc[8..11]: ds a-part | acc[12..15]: ds x raw

    // Relu gate (scalar), rebuild packed x-part
    float q[8], dq[8], xv[8], dsx[8];
    #pragma unroll
    for (int f = 0; f < 4; ++f) {
        unpack2(acc[4 + f],  q[2 * f],  q[2 * f + 1]);
        unpack2(acc[12 + f], dq[2 * f], dq[2 * f + 1]);
    }
    #pragma unroll
    for (int jj = 0; jj < 8; ++jj) {
        const float r = q[jj] - sMu[jj];
        const bool pos = (r > 0.0f);            // JAX relu jvp convention
        xv[jj]  = pos ? r : 0.0f;
        dsx[jj] = pos ? dq[jj] : 0.0f;
    }
    ull stX2[4], dsX2[4], xx[8], aa[8];
    #pragma unroll
    for (int f = 0; f < 4; ++f) {
        stX2[f] = pack2(xv[2 * f],  xv[2 * f + 1]);
        dsX2[f] = pack2(dsx[2 * f], dsx[2 * f + 1]);
    }
    #pragma unroll
    for (int jj = 0; jj < 8; ++jj) xx[jj] = pack2(xv[jj], xv[jj]);
    {
        float a_[8];
        #pragma unroll
        for (int f = 0; f < 4; ++f) unpack2(acc[f], a_[2 * f], a_[2 * f + 1]);
        #pragma unroll
        for (int jj = 0; jj < 8; ++jj) aa[jj] = pack2(a_[jj], a_[jj]);
    }

    // Data loss (packed pairs)
    ull err2 = 0ull;
    const float* xt = x_target + (size_t)b * 16 * TT + ti;
    #pragma unroll
    for (int f = 0; f < 4; ++f) {
        const ull d = sub2(acc[f], pack2(xt[(2 * f) * TT], xt[(2 * f + 1) * TT]));
        err2 = fma2(d, d, err2);
    }
    #pragma unroll
    for (int f = 0; f < 4; ++f) {
        const ull d = sub2(stX2[f], pack2(xt[(8 + 2 * f) * TT], xt[(8 + 2 * f + 1) * TT]));
        err2 = fma2(d, d, err2);
    }

    // Physics (packed row-pairs): da = g + Pi@x - a ; dx = (Gamma@a)*(mu - x)
    #pragma unroll
    for (int e = 0; e < 4; ++e) {
        ull pacc = sG2[e];
        #pragma unroll
        for (int jj = 0; jj < 8; ++jj)
            pacc = fma2(sPi2[jj * 4 + e], xx[jj], pacc);
        const ull da2 = sub2(pacc, acc[e]);
        const ull d1  = sub2(acc[8 + e], da2);
        err2 = fma2(d1, d1, err2);

        ull gacc = 0ull;
        #pragma unroll
        for (int jj = 0; jj < 8; ++jj)
            gacc = fma2(sGa2[jj * 4 + e], aa[jj], gacc);
        const ull mux = sub2(sMu2[e], stX2[e]);
        const ull dx2 = mul2(gacc, mux);
        const ull d2v = sub2(dsX2[e], dx2);
        err2 = fma2(d2v, d2v, err2);
    }
    float elo, ehi; unpack2(err2, elo, ehi);
    float err = elo + ehi;

    // Supervised slice: 9 params elems + 1 ic elem per block
    float sup = 0.0f;
    if (tid < 9) {
        const int i = blockIdx.x * 9 + tid;
        const float d = params_pred[i] - params_target[i];
        sup = d * d;
    } else if (tid == 9) {
        const float d = ic_pred[blockIdx.x] - ic_target[blockIdx.x];
        sup = d * d;
    }

    // Deterministic block reduction
    #pragma unroll
    for (int off = 16; off; off >>= 1) {
        err += __shfl_xor_sync(0xffffffffu, err, off);
        sup += __shfl_xor_sync(0xffffffffu, sup, off);
    }
    __shared__ float sr1[TPB / 32], sr2[TPB / 32];
    if ((tid & 31) == 0) { sr1[tid >> 5] = err; sr2[tid >> 5] = sup; }
    __syncthreads();
    if (tid == 0) {
        float s = 0.0f, ss = 0.0f;
        #pragma unroll
        for (int w = 0; w < TPB / 32; ++w) { s += sr1[w]; ss += sr2[w]; }
        g_partial[blockIdx.x] = s * (1.0f / 16777216.0f) + ss * (1.0f / 40960.0f);
    }
}

__global__ __launch_bounds__(256) void pinn_finalize(float* __restrict__ out)
{
    const int tid = threadIdx.x;
    const float4* p = (const float4*)g_partial;      // 1024 float4
    float s = 0.0f;
    #pragma unroll
    for (int i = tid; i < NBLOCKS / 4; i += 256) {
        const float4 v = p[i];
        s += (v.x + v.y) + (v.z + v.w);
    }
    #pragma unroll
    for (int off = 16; off; off >>= 1)
        s += __shfl_xor_sync(0xffffffffu, s, off);
    __shared__ float r[8];
    if ((tid & 31) == 0) r[tid >> 5] = s;
    __syncthreads();
    if (tid == 0) {
        float a = 0.0f;
        #pragma unroll
        for (int w = 0; w < 8; ++w) a += r[w];
        out[0] = a;
    }
}

extern "C" void kernel_launch(void* const* d_in, const int* in_sizes, int n_in,
                              void* d_out, int out_size) {
    const float* t             = (const float*)d_in[0];
    const float* x_target      = (const float*)d_in[1];
    const float* params_pred   = (const float*)d_in[2];
    const float* params_target = (const float*)d_in[3];
    const float* ic_pred       = (const float*)d_in[4];
    const float* ic_target     = (const float*)d_in[5];
    const float* W1            = (const float*)d_in[6];
    const float* b1            = (const float*)d_in[7];
    const float* W2            = (const float*)d_in[8];
    const float* b2            = (const float*)d_in[9];

    pinn_prep<<<1, 512>>>(W1, b1, W2, b2);
    pinn_point_kernel<<<NBLOCKS, TPB>>>(t, x_target, params_pred, params_target,
                                        ic_pred, ic_target);
    pinn_finalize<<<1, 256>>>((float*)d_out);
}

// round 12
// speedup vs baseline: 1.9133x; 1.0853x over previous
#include <cuda_runtime.h>

// Problem constants
#define BB 256
#define TT 4096
#define HH 64
#define TPB 256
#define CHUNKS (TT / TPB)           // 16
#define NBLOCKS (BB * CHUNKS)       // 4096
#define NC 16                       // Chebyshev fit nodes
#define NCOEF 10                    // retained monomial coeffs (degree 9, economized)
#define NPOLY 32                    // 16 latent + 16 dlatent

typedef unsigned long long ull;

// Deterministic scratch (no atomics on float, no allocation)
__device__ float g_partial[NBLOCKS];
__device__ ull   g_C[NCOEF * 16];   // [m][e] : packed (poly 2e, poly 2e+1) monomial coeff m
__device__ unsigned int g_count = 0;

__device__ __forceinline__ ull pack2(float lo, float hi) {
    ull r; asm("mov.b64 %0, {%1, %2};" : "=l"(r) : "f"(lo), "f"(hi)); return r;
}
__device__ __forceinline__ void unpack2(ull v, float& lo, float& hi) {
    asm("mov.b64 {%0, %1}, %2;" : "=f"(lo), "=f"(hi) : "l"(v));
}
__device__ __forceinline__ ull fma2(ull a, ull b, ull c) {
    ull d; asm("fma.rn.f32x2 %0, %1, %2, %3;" : "=l"(d) : "l"(a), "l"(b), "l"(c)); return d;
}
__device__ __forceinline__ ull add2(ull a, ull b) {
    ull d; asm("add.rn.f32x2 %0, %1, %2;" : "=l"(d) : "l"(a), "l"(b)); return d;
}
__device__ __forceinline__ ull mul2(ull a, ull b) {
    ull d; asm("mul.rn.f32x2 %0, %1, %2;" : "=l"(d) : "l"(a), "l"(b)); return d;
}
__device__ __forceinline__ ull sub2(ull a, ull b) {
    return add2(a, b ^ 0x8000000080000000ULL);
}

// ───────────────────────────── prep: fit polynomials ───────────────────────
// poly j (0..15)  = latent_j(t)  (includes b2) ; poly j (16..31) = d latent/dt
__global__ __launch_bounds__(512) void pinn_prep(
    const float* __restrict__ W1, const float* __restrict__ b1,
    const float* __restrict__ W2, const float* __restrict__ b2)
{
    __shared__ double sCos[64];           // cos(pi*k/32)
    __shared__ float  sW2[HH * 16];       // [k][jj]
    __shared__ float  sH [HH * 16];       // [k][i] tanh values (i = node)
    __shared__ float  sHP[HH * 16];       // [k][i] (1-h^2)*w1k
    __shared__ double sF[NPOLY][NC];      // node values
    __shared__ double sC[NPOLY][NCOEF];   // Chebyshev coeffs (truncated)
    __shared__ double sT[NCOEF][NC];      // T_m monomial coeffs (exact integers)
    __shared__ float  sA[NPOLY][NCOEF];   // monomial coeffs

    const int tid = threadIdx.x;          // 512 = 32 polys x 16 nodes
    const int j = tid >> 4;               // poly
    const int i = tid & 15;               // node / coeff index

    // Phase 0: cosine table + stage W2
    if (tid < 64) sCos[tid] = cospi((double)tid / 32.0);
    sW2[tid] = W2[tid];
    sW2[tid + 512] = W2[tid + 512];
    __syncthreads();

    // Phase 1a: tanh table, 1024 (k,i) pairs, 2 per thread — the ONLY tanh evals
    #pragma unroll
    for (int p = tid; p < HH * 16; p += 512) {
        const int k = p >> 4, ii = p & 15;
        const float tv  = (float)(0.5 + 0.5 * sCos[2 * ii + 1]);
        const float w1k = W1[k];
        const float h   = tanhf(fmaf(tv, w1k, b1[k]));
        sH [p] = h;
        sHP[p] = (1.0f - h * h) * w1k;
    }
    __syncthreads();

    // Phase 1b: node values — fp32 with 4 split accumulators ([k][i] layout: conflict-free)
    {
        const int jj = j & 15;
        const bool isD = (j >= 16);
        const float* tab = isD ? sHP : sH;
        float a0 = 0.f, a1 = 0.f, a2 = 0.f, a3 = 0.f;
        #pragma unroll
        for (int k = 0; k < HH; k += 4) {
            a0 = fmaf(tab[(k + 0) * 16 + i], sW2[(k + 0) * 16 + jj], a0);
            a1 = fmaf(tab[(k + 1) * 16 + i], sW2[(k + 1) * 16 + jj], a1);
            a2 = fmaf(tab[(k + 2) * 16 + i], sW2[(k + 2) * 16 + jj], a2);
            a3 = fmaf(tab[(k + 3) * 16 + i], sW2[(k + 3) * 16 + jj], a3);
        }
        sF[j][i] = (double)((a0 + a1) + (a2 + a3)) + (isD ? 0.0 : (double)b2[jj]);
    }
    __syncthreads();

    // Phase 2: DCT -> Chebyshev coeffs (m < NCOEF): cos table index (m*(2q+1)) & 63
    if (i < NCOEF) {
        const int m = i;
        double s = 0.0;
        #pragma unroll
        for (int q = 0; q < NC; ++q)
            s += sF[j][q] * sCos[(m * (2 * q + 1)) & 63];
        sC[j][m] = s * ((m == 0) ? (1.0 / NC) : (2.0 / NC));
    }

    // Phase 3: T_m monomial table rows 0..NCOEF-1, parallel recurrence
    if (tid < NCOEF * NC) {
        const int m = tid >> 4, p = tid & 15;
        sT[m][p] = 0.0;
    }
    __syncthreads();
    if (tid == 0) sT[0][0] = 1.0;
    if (tid == 1) sT[1][1] = 1.0;
    for (int m = 2; m < NCOEF; ++m) {
        __syncthreads();
        if (tid < NC) {
            const int p = tid;
            double v = -sT[m - 2][p];
            if (p > 0) v += 2.0 * sT[m - 1][p - 1];
            sT[m][p] = v;
        }
    }
    __syncthreads();

    // Phase 4: Chebyshev -> monomial (fp64, then narrow)
    if (i < NCOEF) {
        const int p = i;
        double a = 0.0;
        for (int m = p; m < NCOEF; ++m) a += sC[j][m] * sT[m][p];
        sA[j][p] = (float)a;
    }
    __syncthreads();

    // Phase 5: pack j-pairs: g_C[m*16 + e] = (poly 2e, poly 2e+1) coeff m
    if (tid < NCOEF * 16) {
        const int m = tid >> 4, e = tid & 15;
        g_C[m * 16 + e] = pack2(sA[2 * e][m], sA[2 * e + 1][m]);
    }
}

// ───────────────────────────── point kernel (+fused final reduce) ──────────
__global__ __launch_bounds__(TPB) void pinn_point_kernel(
    const float* __restrict__ t,
    const float* __restrict__ x_target,
    const float* __restrict__ params_pred,
    const float* __restrict__ params_target,
    const float* __restrict__ ic_pred,
    const float* __restrict__ ic_target,
    float* __restrict__ out)
{
    __shared__ ull  sCm[NCOEF * 16]; // [m][e]
    __shared__ ull  sPi2[8 * 4];     // [j][e] = (Pi[2e][j], Pi[2e+1][j])
    __shared__ ull  sGa2[8 * 4];     // [j][e] = (Ga[2e][j], Ga[2e+1][j])
    __shared__ ull  sG2[4];          // g pairs
    __shared__ ull  sMu2[4];         // mu pairs
    __shared__ float sMu[8];

    const int b     = blockIdx.x >> 4;
    const int chunk = blockIdx.x & (CHUNKS - 1);
    const int tid   = threadIdx.x;
    const float* pp = params_pred + b * 144;

    // Stage coefficients + packed per-batch params
    if (tid < NCOEF * 16) sCm[tid] = g_C[tid];
    if (tid >= 192 && tid < 224) {                // Pi packed by row-pairs
        const int q2 = tid - 192, jj = q2 >> 2, e = q2 & 3;
        sPi2[jj * 4 + e] = pack2(pp[16 + (2 * e) * 8 + jj], pp[16 + (2 * e + 1) * 8 + jj]);
    } else if (tid >= 224) {                      // Gamma packed by row-pairs
        const int q2 = tid - 224, jj = q2 >> 2, e = q2 & 3;
        sGa2[jj * 4 + e] = pack2(pp[80 + (2 * e) * 8 + jj], pp[80 + (2 * e + 1) * 8 + jj]);
    } else if (tid >= 176 && tid < 180) {
        const int e = tid - 176; sG2[e] = pack2(pp[2 * e], pp[2 * e + 1]);
    } else if (tid >= 180 && tid < 184) {
        const int e = tid - 180; sMu2[e] = pack2(pp[8 + 2 * e], pp[8 + 2 * e + 1]);
    } else if (tid >= 184 && tid < 192) {
        sMu[tid - 184] = pp[8 + (tid - 184)];
    }
    __syncthreads();

    const int   ti = chunk * TPB + tid;
    const float tv = t[b * TT + ti];
    const float u  = fmaf(2.0f, tv, -1.0f);
    const ull   uu = pack2(u, u);

    // 16 packed Horner evaluations (lat pairs e=0..7, dlat pairs e=8..15)
    const ulonglong2* C2 = (const ulonglong2*)sCm;
    ull acc[16];
    #pragma unroll
    for (int f = 0; f < 8; ++f) {
        const ulonglong2 c = C2[(NCOEF - 1) * 8 + f];
        acc[2 * f] = c.x; acc[2 * f + 1] = c.y;
    }
    #pragma unroll
    for (int m = NCOEF - 2; m >= 0; --m) {
        #pragma unroll
        for (int f = 0; f < 8; ++f) {
            const ulonglong2 c = C2[m * 8 + f];
            acc[2 * f]     = fma2(uu, acc[2 * f],     c.x);
            acc[2 * f + 1] = fma2(uu, acc[2 * f + 1], c.y);
        }
    }
    // acc[0..3]: a-part st pairs | acc[4..7]: q pairs | acc[8..11]: ds a-part | acc[12..15]: ds x raw

    // Relu gate (scalar), rebuild packed x-part
    float q[8], dq[8], xv[8], dsx[8];
    #pragma unroll
    for (int f = 0; f < 4; ++f) {
        unpack2(acc[4 + f],  q[2 * f],  q[2 * f + 1]);
        unpack2(acc[12 + f], dq[2 * f], dq[2 * f + 1]);
    }
    #pragma unroll
    for (int jj = 0; jj < 8; ++jj) {
        const float r = q[jj] - sMu[jj];
        const bool pos = (r > 0.0f);            // JAX relu jvp convention
        xv[jj]  = pos ? r : 0.0f;
        dsx[jj] = pos ? dq[jj] : 0.0f;
    }
    ull stX2[4], dsX2[4], xx[8], aa[8];
    #pragma unroll
    for (int f = 0; f < 4; ++f) {
        stX2[f] = pack2(xv[2 * f],  xv[2 * f + 1]);
        dsX2[f] = pack2(dsx[2 * f], dsx[2 * f + 1]);
    }
    #pragma unroll
    for (int jj = 0; jj < 8; ++jj) xx[jj] = pack2(xv[jj], xv[jj]);
    {
        float a_[8];
        #pragma unroll
        for (int f = 0; f < 4; ++f) unpack2(acc[f], a_[2 * f], a_[2 * f + 1]);
        #pragma unroll
        for (int jj = 0; jj < 8; ++jj) aa[jj] = pack2(a_[jj], a_[jj]);
    }

    // Data loss (packed pairs)
    ull err2 = 0ull;
    const float* xt = x_target + (size_t)b * 16 * TT + ti;
    #pragma unroll
    for (int f = 0; f < 4; ++f) {
        const ull d = sub2(acc[f], pack2(xt[(2 * f) * TT], xt[(2 * f + 1) * TT]));
        err2 = fma2(d, d, err2);
    }
    #pragma unroll
    for (int f = 0; f < 4; ++f) {
        const ull d = sub2(stX2[f], pack2(xt[(8 + 2 * f) * TT], xt[(8 + 2 * f + 1) * TT]));
        err2 = fma2(d, d, err2);
    }

    // Physics (packed row-pairs): da = g + Pi@x - a ; dx = (Gamma@a)*(mu - x)
    #pragma unroll
    for (int e = 0; e < 4; ++e) {
        ull pacc = sG2[e];
        #pragma unroll
        for (int jj = 0; jj < 8; ++jj)
            pacc = fma2(sPi2[jj * 4 + e], xx[jj], pacc);
        const ull da2 = sub2(pacc, acc[e]);
        const ull d1  = sub2(acc[8 + e], da2);
        err2 = fma2(d1, d1, err2);

        ull gacc = 0ull;
        #pragma unroll
        for (int jj = 0; jj < 8; ++jj)
            gacc = fma2(sGa2[jj * 4 + e], aa[jj], gacc);
        const ull mux = sub2(sMu2[e], stX2[e]);
        const ull dx2 = mul2(gacc, mux);
        const ull d2v = sub2(dsX2[e], dx2);
        err2 = fma2(d2v, d2v, err2);
    }
    float elo, ehi; unpack2(err2, elo, ehi);
    float err = elo + ehi;

    // Supervised slice: 9 params elems + 1 ic elem per block
    float sup = 0.0f;
    if (tid < 9) {
        const int i = blockIdx.x * 9 + tid;
        const float d = params_pred[i] - params_target[i];
        sup = d * d;
    } else if (tid == 9) {
        const float d = ic_pred[blockIdx.x] - ic_target[blockIdx.x];
        sup = d * d;
    }

    // Deterministic block reduction
    #pragma unroll
    for (int off = 16; off; off >>= 1) {
        err += __shfl_xor_sync(0xffffffffu, err, off);
        sup += __shfl_xor_sync(0xffffffffu, sup, off);
    }
    __shared__ float sr1[TPB / 32], sr2[TPB / 32];
    if ((tid & 31) == 0) { sr1[tid >> 5] = err; sr2[tid >> 5] = sup; }
    __syncthreads();
    if (tid == 0) {
        float s = 0.0f, ss = 0.0f;
        #pragma unroll
        for (int w = 0; w < TPB / 32; ++w) { s += sr1[w]; ss += sr2[w]; }
        g_partial[blockIdx.x] = s * (1.0f / 16777216.0f) + ss * (1.0f / 40960.0f);
    }

    // Fused finalize: last block to arrive reduces all partials (fixed order
    // -> deterministic result regardless of which block is last).
    __shared__ bool isLast;
    __threadfence();
    if (tid == 0) {
        const unsigned int old = atomicAdd(&g_count, 1u);
        isLast = (old == NBLOCKS - 1);
    }
    __syncthreads();
    if (isLast) {
        const float4* p = (const float4*)g_partial;      // 1024 float4
        float s = 0.0f;
        #pragma unroll
        for (int i = tid; i < NBLOCKS / 4; i += TPB) {
            const float4 v = p[i];
            s += (v.x + v.y) + (v.z + v.w);
        }
        #pragma unroll
        for (int off = 16; off; off >>= 1)
            s += __shfl_xor_sync(0xffffffffu, s, off);
        if ((tid & 31) == 0) sr1[tid >> 5] = s;
        __syncthreads();
        if (tid == 0) {
            float a = 0.0f;
            #pragma unroll
            for (int w = 0; w < TPB / 32; ++w) a += sr1[w];
            out[0] = a;
            g_count = 0;                                  // reset for next replay
        }
    }
}

extern "C" void kernel_launch(void* const* d_in, const int* in_sizes, int n_in,
                              void* d_out, int out_size) {
    const float* t             = (const float*)d_in[0];
    const float* x_target      = (const float*)d_in[1];
    const float* params_pred   = (const float*)d_in[2];
    const float* params_target = (const float*)d_in[3];
    const float* ic_pred       = (const float*)d_in[4];
    const float* ic_target     = (const float*)d_in[5];
    const float* W1            = (const float*)d_in[6];
    const float* b1            = (const float*)d_in[7];
    const float* W2            = (const float*)d_in[8];
    const float* b2            = (const float*)d_in[9];

    pinn_prep<<<1, 512>>>(W1, b1, W2, b2);
    pinn_point_kernel<<<NBLOCKS, TPB>>>(t, x_target, params_pred, params_target,
                                        ic_pred, ic_target, (float*)d_out);
}